// round 2
// baseline (speedup 1.0000x reference)
#include <cuda_runtime.h>
#include <math.h>

#define TILE 128
#define THREADS 256

// Scratch accumulator (no device allocation allowed in kernel_launch).
__device__ double g_acc;

__global__ void zero_acc_kernel() {
    g_acc = 0.0;
}

__global__ __launch_bounds__(THREADS)
void depth_loss_tiles(const float* __restrict__ p,
                      const float* __restrict__ z_spacing,
                      const float* __restrict__ nth_slice,
                      int n)
{
    __shared__ float sp_row[TILE];
    __shared__ float sp_col[TILE];
    __shared__ float warp_sums[THREADS / 32];

    const float a = z_spacing[0] * nth_slice[0];   // STEP == 1.0
    const float c1 = -0.2f * a;
    const float c2 = -0.8f * a;

    // Map linear block id -> lower-triangular tile (ti >= tj)
    int t  = blockIdx.x;
    int ti = (int)((sqrtf(8.0f * (float)t + 1.0f) - 1.0f) * 0.5f);
    while ((ti + 1) * (ti + 2) / 2 <= t) ti++;
    while (ti * (ti + 1) / 2 > t) ti--;
    int tj = t - ti * (ti + 1) / 2;

    const int i0 = ti * TILE;
    const int j0 = tj * TILE;
    const int tid = threadIdx.x;

    // Stage row-slice and col-slice of p into shared memory.
    if (tid < TILE) sp_row[tid] = p[i0 + tid];
    else            sp_col[tid - TILE] = p[j0 + (tid - TILE)];
    __syncthreads();

    // 256 threads cover 128x128 pairs: 2 threads per row, 64 cols each.
    const int   li    = tid >> 1;
    const int   jbase = (tid & 1) * 64;
    const float pr    = sp_row[li];
    // (global i - global j) for k=0, as float; decreases by 1 per column.
    float tdiff0 = (float)((i0 + li) - (j0 + jbase));

    float acc = 0.0f;

    if (ti != tj) {
        // Off-diagonal tile: every pair has i > j, no mask needed.
        #pragma unroll 16
        for (int k = 0; k < 64; ++k) {
            float pc    = sp_col[jbase + k];
            float tdiff = tdiff0 - (float)k;
            float d  = pr - pc;
            d = (d >= 0.0f) ? fmaf(c1, tdiff, d) : d;
            d = (d >= 0.0f) ? fmaxf(fmaf(c2, tdiff, d), 0.0f) : d;
            acc += fabsf(d);
        }
    } else {
        // Diagonal tile: mask out i < j (tdiff < 0). i == j contributes 0.
        #pragma unroll 16
        for (int k = 0; k < 64; ++k) {
            float pc    = sp_col[jbase + k];
            float tdiff = tdiff0 - (float)k;
            float d  = pr - pc;
            d = (d >= 0.0f) ? fmaf(c1, tdiff, d) : d;
            d = (d >= 0.0f) ? fmaxf(fmaf(c2, tdiff, d), 0.0f) : d;
            acc += (tdiff >= 0.0f) ? fabsf(d) : 0.0f;
        }
    }

    // Warp reduction
    #pragma unroll
    for (int off = 16; off > 0; off >>= 1)
        acc += __shfl_xor_sync(0xFFFFFFFFu, acc, off);
    if ((tid & 31) == 0) warp_sums[tid >> 5] = acc;
    __syncthreads();

    if (tid < (THREADS / 32)) {
        float v = warp_sums[tid];
        #pragma unroll
        for (int off = (THREADS / 64); off > 0; off >>= 1)
            v += __shfl_xor_sync(0xFFu, v, off);
        if (tid == 0)
            atomicAdd(&g_acc, (double)v);
    }
}

__global__ void finalize_kernel(float* __restrict__ out, double inv_nn) {
    out[0] = (float)(g_acc * inv_nn);
}

extern "C" void kernel_launch(void* const* d_in, const int* in_sizes, int n_in,
                              void* d_out, int out_size)
{
    const float* p   = (const float*)d_in[0];   // predictions (N,1) fp32
    const float* zs  = (const float*)d_in[1];   // z_spacing scalar
    const float* ns  = (const float*)d_in[2];   // nth_slice scalar
    float* out = (float*)d_out;

    const int n = in_sizes[0];
    const int T = n / TILE;                      // 64 for N=8192
    const int n_tiles = T * (T + 1) / 2;         // 2080

    zero_acc_kernel<<<1, 1>>>();
    depth_loss_tiles<<<n_tiles, THREADS>>>(p, zs, ns, n);
    finalize_kernel<<<1, 1>>>(out, 1.0 / ((double)n * (double)n));
}

// round 5
// speedup vs baseline: 1.1047x; 1.1047x over previous
#include <cuda_runtime.h>
#include <math.h>

#define TILE 128
#define THREADS 256

// Scratch accumulator + completion counter (no device allocation allowed).
__device__ double       g_acc   = 0.0;
__device__ unsigned int g_count = 0u;

__global__ __launch_bounds__(THREADS)
void depth_loss_fused(const float* __restrict__ p,
                      const float* __restrict__ z_spacing,
                      const float* __restrict__ nth_slice,
                      float* __restrict__ out,
                      int n, int n_blocks)
{
    __shared__ float sp_row[TILE];
    __shared__ float sp_col[TILE];
    __shared__ float warp_sums[THREADS / 32];

    const float a  = z_spacing[0] * nth_slice[0];   // STEP == 1.0
    const float c1 = -0.2f * a;
    const float c2 = -0.8f * a;

    // Map linear block id -> lower-triangular tile (ti >= tj)
    int t  = blockIdx.x;
    int ti = (int)((sqrtf(8.0f * (float)t + 1.0f) - 1.0f) * 0.5f);
    while ((ti + 1) * (ti + 2) / 2 <= t) ti++;
    while (ti * (ti + 1) / 2 > t) ti--;
    int tj = t - ti * (ti + 1) / 2;

    const int i0  = ti * TILE;
    const int j0  = tj * TILE;
    const int tid = threadIdx.x;

    // Stage row-slice and col-slice of p into shared memory.
    if (tid < TILE) sp_row[tid] = p[i0 + tid];
    else            sp_col[tid - TILE] = p[j0 + (tid - TILE)];
    __syncthreads();

    // 256 threads cover 128x128 pairs: 2 threads per row, 64 cols each.
    const int   li    = tid >> 1;
    const int   jbase = (tid & 1) * 64;
    const float pr    = sp_row[li];
    float tdiff = (float)((i0 + li) - (j0 + jbase));   // decreases by 1 per col

    float acc = 0.0f;

    if (ti != tj) {
        // Off-diagonal tile: every pair has i > j, no mask needed.
        #pragma unroll
        for (int k = 0; k < 64; ++k) {
            float pc = sp_col[jbase + k];
            float d  = pr - pc;
            // predicated-FMA form: only update d when the guard holds
            if (d >= 0.0f) d = fmaf(c1, tdiff, d);
            if (d >= 0.0f) d = fmaxf(fmaf(c2, tdiff, d), 0.0f);
            acc += fabsf(d);
            tdiff -= 1.0f;
        }
    } else {
        // Diagonal tile: mask out i < j (tdiff < 0). i == j contributes 0.
        #pragma unroll
        for (int k = 0; k < 64; ++k) {
            float pc = sp_col[jbase + k];
            float d  = pr - pc;
            if (d >= 0.0f) d = fmaf(c1, tdiff, d);
            if (d >= 0.0f) d = fmaxf(fmaf(c2, tdiff, d), 0.0f);
            acc += (tdiff >= 0.0f) ? fabsf(d) : 0.0f;
            tdiff -= 1.0f;
        }
    }

    // Warp reduction
    #pragma unroll
    for (int off = 16; off > 0; off >>= 1)
        acc += __shfl_xor_sync(0xFFFFFFFFu, acc, off);
    if ((tid & 31) == 0) warp_sums[tid >> 5] = acc;
    __syncthreads();

    if (tid == 0) {
        float v = 0.0f;
        #pragma unroll
        for (int w = 0; w < THREADS / 32; ++w) v += warp_sums[w];

        atomicAdd(&g_acc, (double)v);
        __threadfence();
        // atomicInc wraps to 0 when old == n_blocks-1 -> counter self-resets
        unsigned old = atomicInc(&g_count, (unsigned)(n_blocks - 1));
        if (old == (unsigned)(n_blocks - 1)) {
            // Last block: all partials are visible. Publish and reset.
            double total = *((volatile double*)&g_acc);
            out[0] = (float)(total / ((double)n * (double)n));
            g_acc = 0.0;   // reset for next graph replay
        }
    }
}

extern "C" void kernel_launch(void* const* d_in, const int* in_sizes, int n_in,
                              void* d_out, int out_size)
{
    const float* p  = (const float*)d_in[0];   // predictions (N,1) fp32
    const float* zs = (const float*)d_in[1];   // z_spacing scalar
    const float* ns = (const float*)d_in[2];   // nth_slice scalar
    float* out = (float*)d_out;

    const int n = in_sizes[0];
    const int T = n / TILE;                    // 64 for N=8192
    const int n_tiles = T * (T + 1) / 2;       // 2080

    depth_loss_fused<<<n_tiles, THREADS>>>(p, zs, ns, out, n, n_tiles);
}